// round 6
// baseline (speedup 1.0000x reference)
#include <cuda_runtime.h>

// QuantumConv1d, single fused kernel (smem <= 48KB static).
//  Phase 0 (overlapped): warp0 folds circuit -> 4 quadratic forms Q_q (4x4);
//                        warps 1-15 stage x tile + weights into smem.
//  Phase 1: conv(K=3): thread (pos=tid>>2, grp=tid&3) does 20 channels;
//           quad-level __shfl_xor reduction -> pre[4]; each thread computes
//           its one quadratic form e[grp] -> ez_s[pos][grp].
//  Phase 2: 16 warps sweep o: out[b,o,l] = W_post[o,:].ez + b_post[o],
//           float4 streaming stores (196.6MB, the roofline term).

#define C_IN     80
#define L_IN     3000
#define OUT_CH   512
#define KW       3
#define TILE_L   128
#define THREADS  512
#define C_PER_G  (C_IN / 4)           // 20 channels per quad lane

__global__ __launch_bounds__(THREADS)
void qconv_fused(const float* __restrict__ x,
                 const float* __restrict__ W_pre,
                 const float* __restrict__ b_pre,
                 const float* __restrict__ W_post,
                 const float* __restrict__ b_post,
                 const float* __restrict__ qw,
                 float* __restrict__ out)
{
    __shared__ float x_s[C_IN][TILE_L + 2];     // 41.6 KB
    __shared__ float w_s[C_IN * 12];            // [c][k][q] 3.75 KB
    __shared__ float ez_s[TILE_L][4];           // 2 KB
    __shared__ float Q_s[4][16];                // 256 B
    __shared__ float bpre_s[4];

    const int tid = threadIdx.x;
    const int b   = blockIdx.y;
    const int l0  = blockIdx.x * TILE_L;

    // ============ Phase 0: Q on warp 0 || staging on warps 1-15 ============
    if (tid < 32) {
        const int k = tid & 3;
        float sr[16], si[16];
        #pragma unroll
        for (int j = 0; j < 16; j++) { sr[j] = 0.f; si[j] = 0.f; }
        #pragma unroll
        for (int j = 0; j < 4; j++) if (j == k) sr[j] = 1.f;

        #pragma unroll
        for (int i = 0; i < 4; i++) {
            float phi = __ldg(qw + i * 3 + 0), th = __ldg(qw + i * 3 + 1), om = __ldg(qw + i * 3 + 2);
            float sh, ch; __sincosf(0.5f * th, &sh, &ch);
            float a = 0.5f * (phi + om), d = 0.5f * (phi - om);
            float sa, ca, sd, cd;
            __sincosf(a, &sa, &ca);
            __sincosf(d, &sd, &cd);
            float u00r =  ch * ca, u00i = -ch * sa;
            float u01r = -sh * cd, u01i = -sh * sd;
            float u10r =  sh * cd, u10i = -sh * sd;
            float u11r =  ch * ca, u11i =  ch * sa;
            const int s = 8 >> i;
            #pragma unroll
            for (int j = 0; j < 16; j++) {
                if ((j & s) == 0) {
                    const int j1 = j | s;
                    float ar = sr[j],  ai = si[j];
                    float br = sr[j1], bi = si[j1];
                    sr[j]  = u00r * ar - u00i * ai + u01r * br - u01i * bi;
                    si[j]  = u00r * ai + u00i * ar + u01r * bi + u01i * br;
                    sr[j1] = u10r * ar - u10i * ai + u11r * br - u11i * bi;
                    si[j1] = u10r * ai + u10i * ar + u11r * bi + u11i * br;
                }
            }
        }
        #define SWP(A,B) { float t; t=sr[A]; sr[A]=sr[B]; sr[B]=t; t=si[A]; si[A]=si[B]; si[B]=t; }
        SWP(8,12) SWP(9,13) SWP(10,14) SWP(11,15)   // cnot(0,1)
        SWP(4,6)  SWP(5,7)  SWP(12,14) SWP(13,15)   // cnot(1,2)
        SWP(2,3)  SWP(6,7)  SWP(10,11) SWP(14,15)   // cnot(2,3)
        #undef SWP

        float Qv[4][4];
        #pragma unroll
        for (int q = 0; q < 4; q++)
            #pragma unroll
            for (int m = 0; m < 4; m++) Qv[q][m] = 0.f;
        #pragma unroll
        for (int j = 0; j < 16; j++) {
            #pragma unroll
            for (int m = 0; m < 4; m++) {
                float arm = __shfl_sync(0xffffffffu, sr[j], m);
                float aim = __shfl_sync(0xffffffffu, si[j], m);
                float p = sr[j] * arm + si[j] * aim;
                Qv[0][m] += (j & 8) ? -p : p;
                Qv[1][m] += (j & 4) ? -p : p;
                Qv[2][m] += (j & 2) ? -p : p;
                Qv[3][m] += (j & 1) ? -p : p;
            }
        }
        if (tid < 4) {
            #pragma unroll
            for (int q = 0; q < 4; q++)
                #pragma unroll
                for (int m = 0; m < 4; m++)
                    Q_s[q][tid * 4 + m] = Qv[q][m];
            bpre_s[tid] = b_pre[tid];
        }
    } else {
        const int t = tid - 32;                     // 0..479
        for (int i = t; i < C_IN * 12; i += THREADS - 32) {
            int c = i / 12; int r = i - c * 12; int k = r >> 2; int q = r & 3;
            w_s[i] = W_pre[q * (C_IN * KW) + c * KW + k];
        }
        const float* xb = x + (size_t)b * C_IN * L_IN;
        for (int i = t; i < C_IN * (TILE_L + 2); i += THREADS - 32) {
            int c = i / (TILE_L + 2);
            int j = i - c * (TILE_L + 2);
            int l = l0 - 1 + j;
            x_s[c][j] = (l >= 0 && l < L_IN) ? xb[c * L_IN + l] : 0.0f;
        }
    }
    __syncthreads();

    // ============ Phase 1: conv partials + quad shuffle reduce + quadratic form ======
    {
        const int pos = tid >> 2;                   // 0..127
        const int grp = tid & 3;                    // 0..3
        const int c0  = grp * C_PER_G;

        float v0 = 0.f, v1 = 0.f, v2 = 0.f, v3 = 0.f;
        #pragma unroll
        for (int ci = 0; ci < C_PER_G; ci++) {
            const int c = c0 + ci;
            float xa = x_s[c][pos], xb1 = x_s[c][pos + 1], xc = x_s[c][pos + 2];
            const float4* wr = (const float4*)&w_s[c * 12];
            float4 w0 = wr[0], w1 = wr[1], w2 = wr[2];
            v0 += w0.x * xa + w1.x * xb1 + w2.x * xc;
            v1 += w0.y * xa + w1.y * xb1 + w2.y * xc;
            v2 += w0.z * xa + w1.z * xb1 + w2.z * xc;
            v3 += w0.w * xa + w1.w * xb1 + w2.w * xc;
        }
        // quad reduction (lanes 4p..4p+3 hold partials for position p)
        v0 += __shfl_xor_sync(0xffffffffu, v0, 1);
        v1 += __shfl_xor_sync(0xffffffffu, v1, 1);
        v2 += __shfl_xor_sync(0xffffffffu, v2, 1);
        v3 += __shfl_xor_sync(0xffffffffu, v3, 1);
        v0 += __shfl_xor_sync(0xffffffffu, v0, 2);
        v1 += __shfl_xor_sync(0xffffffffu, v1, 2);
        v2 += __shfl_xor_sync(0xffffffffu, v2, 2);
        v3 += __shfl_xor_sync(0xffffffffu, v3, 2);

        v0 += bpre_s[0]; v1 += bpre_s[1]; v2 += bpre_s[2]; v3 += bpre_s[3];

        const float inv = __frcp_rn(v0 * v0 + v1 * v1 + v2 * v2 + v3 * v3);
        // this thread's qubit = grp: e = v^T Q[grp] v * inv
        const float* Qr = &Q_s[grp][0];
        float s;
        s  = v0 * (Qr[0]  * v0 + Qr[1]  * v1 + Qr[2]  * v2 + Qr[3]  * v3);
        s += v1 * (Qr[4]  * v0 + Qr[5]  * v1 + Qr[6]  * v2 + Qr[7]  * v3);
        s += v2 * (Qr[8]  * v0 + Qr[9]  * v1 + Qr[10] * v2 + Qr[11] * v3);
        s += v3 * (Qr[12] * v0 + Qr[13] * v1 + Qr[14] * v2 + Qr[15] * v3);
        ez_s[pos][grp] = s * inv;
    }
    __syncthreads();

    // ============ Phase 2: 4->512 broadcast + streaming float4 stores ============
    const int lane = tid & 31;
    const int wrp  = tid >> 5;                  // 0..15
    const int l4   = l0 + lane * 4;
    if (l4 >= L_IN) return;                     // L_IN % 4 == 0: no straddle

    const float4* ez4 = (const float4*)ez_s;
    const float4 e0 = ez4[lane * 4 + 0];
    const float4 e1 = ez4[lane * 4 + 1];
    const float4 e2 = ez4[lane * 4 + 2];
    const float4 e3 = ez4[lane * 4 + 3];

    float* outb = out + (size_t)b * OUT_CH * L_IN;

    #pragma unroll 8
    for (int o = wrp; o < OUT_CH; o += 16) {
        const float4 wp = __ldg((const float4*)(W_post + o * 4));
        const float  bp = __ldg(b_post + o);
        float4 r;
        r.x = fmaf(wp.x, e0.x, fmaf(wp.y, e0.y, fmaf(wp.z, e0.z, fmaf(wp.w, e0.w, bp))));
        r.y = fmaf(wp.x, e1.x, fmaf(wp.y, e1.y, fmaf(wp.z, e1.z, fmaf(wp.w, e1.w, bp))));
        r.z = fmaf(wp.x, e2.x, fmaf(wp.y, e2.y, fmaf(wp.z, e2.z, fmaf(wp.w, e2.w, bp))));
        r.w = fmaf(wp.x, e3.x, fmaf(wp.y, e3.y, fmaf(wp.z, e3.z, fmaf(wp.w, e3.w, bp))));
        __stcs((float4*)(outb + (size_t)o * L_IN + l4), r);
    }
}

extern "C" void kernel_launch(void* const* d_in, const int* in_sizes, int n_in,
                              void* d_out, int out_size)
{
    const float* x      = (const float*)d_in[0];
    const float* W_pre  = (const float*)d_in[1];
    const float* b_pre  = (const float*)d_in[2];
    const float* W_post = (const float*)d_in[3];
    const float* b_post = (const float*)d_in[4];
    const float* qw     = (const float*)d_in[5];
    float* out = (float*)d_out;

    const int B = in_sizes[0] / (C_IN * L_IN);            // 32
    const int n_tiles = (L_IN + TILE_L - 1) / TILE_L;     // 24

    dim3 grid(n_tiles, B);
    qconv_fused<<<grid, THREADS>>>(x, W_pre, b_pre, W_post, b_post, qw, out);
}